// round 7
// baseline (speedup 1.0000x reference)
#include <cuda_runtime.h>
#include <cuda_bf16.h>

// 6-level cascaded db4 DWT, zero-padding mode, fully fused in one kernel.
// Chunked version: each thread produces 4 consecutive outputs per level
// iteration via 4x LDS.128 reads of the 14-float sliding window.
//
// Zero-pad invariant (verified by induction): any buffer slot whose global
// index g is outside [0, LEN) holds EXACTLY 0.0f, because its inputs
// (indices 2g-6..2g+1) are all outside the previous level's valid range
// (2g-6 >= N for g >= M=(N+7)//2; left halo is loaded as zeros). Hence
// sout writes need no guard; only global stores are guarded.

#define TPB 256
#define TT  64   // level-6 outputs per block

__device__ __constant__ float RLO[8] = {
     0.23037781330885523f,  0.7148465705525415f,   0.6308807679295904f,
    -0.02798376941698385f, -0.18703481171888114f,  0.030841381835986965f,
     0.032883011666982945f, -0.010597401784997278f };
__device__ __constant__ float RHI[8] = {
    -0.010597401784997278f, -0.032883011666982945f, 0.030841381835986965f,
     0.18703481171888114f,  -0.02798376941698385f, -0.6308807679295904f,
     0.7148465705525415f,   -0.23037781330885523f };

// Output element-offset layout (row-major [64, M] each), order:
//   a(4102), d6(4102), d5(8198), d4(16390), d3(32774), d2(65541), d1(131075)
//   a:0  d6:262528  d5:525056  d4:1049728  d3:2098688  d2:4196224  d1:8390848

template<int P, int LEN, int H, int DBASE, bool LAST>
__device__ __forceinline__ void level_step(const float* __restrict__ sin,
                                           float* __restrict__ sout,
                                           float* __restrict__ out,
                                           int c, int r, int tid) {
    const int S    = TT * P + H;           // compute-range size at this level
    const int NCH  = (S + 3) / 4;          // 4-output chunks
    const int base = c * (TT * P) - H;     // global index of local 0
    float* __restrict__ dr = out + (size_t)DBASE + (size_t)r * LEN;
    float* __restrict__ ar = out + (size_t)r * LEN;   // only used when LAST

    for (int cb = tid; cb < NCH; cb += TPB) {
        const int j0 = cb * 4;
        // 14-float window sin[8cb .. 8cb+13] via 4x aligned float4 loads
        const float4 va = *(const float4*)(sin + 8 * cb);
        const float4 vb = *(const float4*)(sin + 8 * cb + 4);
        const float4 vc = *(const float4*)(sin + 8 * cb + 8);
        const float4 vd = *(const float4*)(sin + 8 * cb + 12);
        const float v[16] = { va.x, va.y, va.z, va.w,  vb.x, vb.y, vb.z, vb.w,
                              vc.x, vc.y, vc.z, vc.w,  vd.x, vd.y, vd.z, vd.w };
        float lo[4], hi[4];
        #pragma unroll
        for (int i = 0; i < 4; i++) {
            float l = 0.f, h = 0.f;
            #pragma unroll
            for (int m = 0; m < 8; m++) {
                const float vv = v[2 * i + m];
                l = fmaf(vv, RLO[m], l);
                h = fmaf(vv, RHI[m], h);
            }
            lo[i] = l; hi[i] = h;
        }
        if (!LAST)
            *(float4*)(sout + j0) = make_float4(lo[0], lo[1], lo[2], lo[3]);

        const int g0 = base + j0;          // g >= 0 automatic for j >= H
        if (j0 >= H && j0 + 4 <= S && g0 + 4 <= LEN) {
            // interior fast path: unguarded stores
            #pragma unroll
            for (int i = 0; i < 4; i++) {
                dr[g0 + i] = hi[i];
                if (LAST) ar[g0 + i] = lo[i];
            }
        } else {
            #pragma unroll
            for (int i = 0; i < 4; i++) {
                const int j = j0 + i;
                if (j >= H && j < S && (unsigned)(g0 + i) < (unsigned)LEN) {
                    dr[g0 + i] = hi[i];
                    if (LAST) ar[g0 + i] = lo[i];
                }
            }
        }
    }
}

__global__ void __launch_bounds__(TPB)
dwt6_fused_kernel(const float* __restrict__ x, float* __restrict__ out) {
    // Sizes padded so every LDS.128 (up to index 8*(NCH-1)+15) stays in-bounds.
    __shared__ __align__(16) float s0[4480];  // S=4474 (64*TT+378)
    __shared__ __align__(16) float s1[2240];  // S=2234
    __shared__ __align__(16) float s2[1120];  // S=1114
    __shared__ __align__(16) float s3[560];   // S=554
    __shared__ __align__(16) float s4[280];   // S=274
    __shared__ __align__(16) float s5[136];   // S=134

    const int c   = blockIdx.x;
    const int r   = blockIdx.y;
    const int tid = threadIdx.x;

    const float* __restrict__ xr = x + (size_t)r * 262144;
    const int base0 = c * (TT * 64) - 378;    // always even

    // Load input tile + halo (zero-padded) as float2: both base0 and smem
    // index are even -> 8B aligned on both sides.
    for (int jj = tid * 2; jj < 4474; jj += TPB * 2) {
        const int g = base0 + jj;
        float2 vv;
        vv.x = ((unsigned)(g)     < 262144u) ? __ldg(xr + g)     : 0.f;
        vv.y = ((unsigned)(g + 1) < 262144u) ? __ldg(xr + g + 1) : 0.f;
        *(float2*)(s0 + jj) = vv;
    }
    __syncthreads();

    level_step<32, 131075, 186, 8390848, false>(s0, s1, out, c, r, tid);  // d1
    __syncthreads();
    level_step<16,  65541,  90, 4196224, false>(s1, s2, out, c, r, tid);  // d2
    __syncthreads();
    level_step< 8,  32774,  42, 2098688, false>(s2, s3, out, c, r, tid);  // d3
    __syncthreads();
    level_step< 4,  16390,  18, 1049728, false>(s3, s4, out, c, r, tid);  // d4
    __syncthreads();
    level_step< 2,   8198,   6,  525056, false>(s4, s5, out, c, r, tid);  // d5
    __syncthreads();
    level_step< 1,   4102,   0,  262528, true >(s5, (float*)0, out, c, r, tid);  // d6 + a
}

extern "C" void kernel_launch(void* const* d_in, const int* in_sizes, int n_in,
                              void* d_out, int out_size) {
    const float* x = (const float*)d_in[0];
    float* out = (float*)d_out;
    const int rows = in_sizes[0] / 262144;          // 64
    const int chunks = (4102 + TT - 1) / TT;        // 65
    dim3 grid(chunks, rows);
    dwt6_fused_kernel<<<grid, TPB>>>(x, out);
}

// round 8
// speedup vs baseline: 1.2738x; 1.2738x over previous
#include <cuda_runtime.h>
#include <cuda_bf16.h>

// 6-level cascaded db4 DWT, zero-padding mode, fully fused in one kernel.
// One output per thread per iteration; 8-tap window read as 4x LDS.64
// (8B-aligned, 2-wavefront each). Level buffers alias two shared regions
// (A: s0/s2/s4, B: s1/s3/s5) -> 26.9KB smem -> 8 blocks/SM.
//
// Per level: out[i] = sum_{m=0..7} x[2i-6+m] * REV[m], zero outside [0,N).
// M = (N+7)/2. Halo recurrence h_{l-1} = 2*h_l + 6, buffer base
// base_l = c*TT*2^(6-l) - h_l  =>  conv input for local j is sin[2j+m],
// and max read index 2(S_out-1)+7 = S_in-1 exactly fits.

#define TPB 256
#define TT  64   // level-6 outputs per block

#define SZA 4480  // region A: max(4474, 1114, 274), 16B-rounded
#define SZB 2240  // region B: max(2234,  554, 134)

__device__ __constant__ float RLO[8] = {
     0.23037781330885523f,  0.7148465705525415f,   0.6308807679295904f,
    -0.02798376941698385f, -0.18703481171888114f,  0.030841381835986965f,
     0.032883011666982945f, -0.010597401784997278f };
__device__ __constant__ float RHI[8] = {
    -0.010597401784997278f, -0.032883011666982945f, 0.030841381835986965f,
     0.18703481171888114f,  -0.02798376941698385f, -0.6308807679295904f,
     0.7148465705525415f,   -0.23037781330885523f };

// Output element-offset layout (row-major [64, M] each), order:
//   a(4102), d6(4102), d5(8198), d4(16390), d3(32774), d2(65541), d1(131075)
//   a:0  d6:262528  d5:525056  d4:1049728  d3:2098688  d2:4196224  d1:8390848

template<int P, int LEN, int H, int DBASE, bool LAST>
__device__ __forceinline__ void level_step(const float* __restrict__ sin,
                                           float* __restrict__ sout,
                                           float* __restrict__ out,
                                           int c, int r, int tid) {
    const int S    = TT * P + H;           // compute-range size at this level
    const int base = c * (TT * P) - H;     // global index of local 0
    float* __restrict__ dr = out + (size_t)DBASE + (size_t)r * LEN;
    float* __restrict__ ar = out + (size_t)r * LEN;   // only used when LAST

    for (int j = tid; j < S; j += TPB) {
        const int g = base + j;
        float lo = 0.f, hi = 0.f;
        if ((unsigned)g < (unsigned)LEN) {
            const float2 p0 = *(const float2*)(sin + 2 * j);
            const float2 p1 = *(const float2*)(sin + 2 * j + 2);
            const float2 p2 = *(const float2*)(sin + 2 * j + 4);
            const float2 p3 = *(const float2*)(sin + 2 * j + 6);
            const float v[8] = { p0.x, p0.y, p1.x, p1.y,
                                 p2.x, p2.y, p3.x, p3.y };
            #pragma unroll
            for (int m = 0; m < 8; m++) {
                lo = fmaf(v[m], RLO[m], lo);
                hi = fmaf(v[m], RHI[m], hi);
            }
        }
        if (!LAST) sout[j] = lo;                       // zero-pad preserved
        if (j >= H && (unsigned)g < (unsigned)LEN) {   // unique writer
            dr[g] = hi;
            if (LAST) ar[g] = lo;
        }
    }
}

__global__ void __launch_bounds__(TPB)
dwt6_fused_kernel(const float* __restrict__ x, float* __restrict__ out) {
    // Region A holds s0 (L1 in), then s2 (L3 in), then s4 (L5 in).
    // Region B holds s1 (L2 in), then s3 (L4 in), then s5 (L6 in).
    // Each level reads one region and writes the other; __syncthreads()
    // separates the read of a buffer from its overwrite two levels later.
    __shared__ __align__(16) float smA[SZA];
    __shared__ __align__(16) float smB[SZB];

    const int c   = blockIdx.x;
    const int r   = blockIdx.y;
    const int tid = threadIdx.x;

    const float* __restrict__ xr = x + (size_t)r * 262144;
    const int base0 = c * (TT * 64) - 378;    // always even

    // Load input tile + halo (zero-padded) as float2 (both sides 8B-aligned).
    for (int jj = tid * 2; jj < 4474; jj += TPB * 2) {
        const int g = base0 + jj;
        float2 vv;
        vv.x = ((unsigned)(g)     < 262144u) ? __ldg(xr + g)     : 0.f;
        vv.y = ((unsigned)(g + 1) < 262144u) ? __ldg(xr + g + 1) : 0.f;
        *(float2*)(smA + jj) = vv;
    }
    __syncthreads();

    level_step<32, 131075, 186, 8390848, false>(smA, smB, out, c, r, tid);  // d1: s0->s1
    __syncthreads();
    level_step<16,  65541,  90, 4196224, false>(smB, smA, out, c, r, tid);  // d2: s1->s2
    __syncthreads();
    level_step< 8,  32774,  42, 2098688, false>(smA, smB, out, c, r, tid);  // d3: s2->s3
    __syncthreads();
    level_step< 4,  16390,  18, 1049728, false>(smB, smA, out, c, r, tid);  // d4: s3->s4
    __syncthreads();
    level_step< 2,   8198,   6,  525056, false>(smA, smB, out, c, r, tid);  // d5: s4->s5
    __syncthreads();
    level_step< 1,   4102,   0,  262528, true >(smB, (float*)0, out, c, r, tid);  // d6 + a
}

extern "C" void kernel_launch(void* const* d_in, const int* in_sizes, int n_in,
                              void* d_out, int out_size) {
    const float* x = (const float*)d_in[0];
    float* out = (float*)d_out;
    const int rows = in_sizes[0] / 262144;          // 64
    const int chunks = (4102 + TT - 1) / TT;        // 65
    dim3 grid(chunks, rows);
    dwt6_fused_kernel<<<grid, TPB>>>(x, out);
}

// round 13
// speedup vs baseline: 1.9028x; 1.4937x over previous
#include <cuda_runtime.h>
#include <cuda_bf16.h>

// 6-level cascaded db4 DWT, zero-padding mode, fully fused in one kernel.
//
// Level 1 reads x directly from gmem (no smem staging); levels 2-6 read the
// previous cA from smem. Each thread computes an output PAIR (j0, j0+1):
// shared 10-float window loaded as float4+float4+float2 (all aligned, reads
// exactly up to S_in-1). Coefficients are FFMA immediates.
//
// Zero-pad invariant (induction): any buffer slot with global index outside
// [0, LEN) computes to exactly +0.0f because all its inputs are either
// guarded gmem loads (level 1) or out-of-range slots of the previous level.
// So no compute guard is needed; only global stores are predicated.
// Ownership: slot j is stored iff j >= H (H even, j0 even -> pair-uniform)
// and its global index is in [0, LEN). Exactly one block stores each output.

#define TPB 256
#define TT  64   // level-6 outputs per block

// db4 reversed decomposition filters as literals (FFMA-imm form).
#define RL0  0.23037781330885523f
#define RL1  0.7148465705525415f
#define RL2  0.6308807679295904f
#define RL3 -0.02798376941698385f
#define RL4 -0.18703481171888114f
#define RL5  0.030841381835986965f
#define RL6  0.032883011666982945f
#define RL7 -0.010597401784997278f
#define RH0 -0.010597401784997278f
#define RH1 -0.032883011666982945f
#define RH2  0.030841381835986965f
#define RH3  0.18703481171888114f
#define RH4 -0.02798376941698385f
#define RH5 -0.6308807679295904f
#define RH6  0.7148465705525415f
#define RH7 -0.23037781330885523f

// Same accumulation order as the reference kernel: acc starts at 0, taps 0..7.
__device__ __forceinline__ void conv8(const float* v, float& lo, float& hi) {
    float l = 0.f, h = 0.f;
    l = fmaf(v[0], RL0, l);  h = fmaf(v[0], RH0, h);
    l = fmaf(v[1], RL1, l);  h = fmaf(v[1], RH1, h);
    l = fmaf(v[2], RL2, l);  h = fmaf(v[2], RH2, h);
    l = fmaf(v[3], RL3, l);  h = fmaf(v[3], RH3, h);
    l = fmaf(v[4], RL4, l);  h = fmaf(v[4], RH4, h);
    l = fmaf(v[5], RL5, l);  h = fmaf(v[5], RH5, h);
    l = fmaf(v[6], RL6, l);  h = fmaf(v[6], RH6, h);
    l = fmaf(v[7], RL7, l);  h = fmaf(v[7], RH7, h);
    lo = l; hi = h;
}

// Output element-offset layout (row-major [64, M] each), order:
//   a(4102), d6(4102), d5(8198), d4(16390), d3(32774), d2(65541), d1(131075)
//   a:0  d6:262528  d5:525056  d4:1049728  d3:2098688  d2:4196224  d1:8390848

// Levels 2-6: input cA from smem, pair scheme.
template<int P, int LEN, int H, int DBASE, bool LAST>
__device__ __forceinline__ void level_pair(const float* __restrict__ sin,
                                           float* __restrict__ sout,
                                           float* __restrict__ out,
                                           int c, int r, int tid) {
    constexpr int S  = TT * P + H;   // outputs at this level (always even)
    constexpr int NP = S / 2;
    const int base = c * (TT * P) - H;
    float* __restrict__ dr = out + (size_t)DBASE + (size_t)r * LEN;
    float* __restrict__ ar = out + (size_t)r * LEN;   // only when LAST

    for (int jp = tid; jp < NP; jp += TPB) {
        const int j0 = 2 * jp;
        // window sin[2j0 .. 2j0+9]: out0 uses v[0..7], out1 uses v[2..9]
        const float4 a4 = *(const float4*)(sin + 2 * j0);
        const float4 b4 = *(const float4*)(sin + 2 * j0 + 4);
        const float2 c2 = *(const float2*)(sin + 2 * j0 + 8);
        const float v[10] = { a4.x, a4.y, a4.z, a4.w,
                              b4.x, b4.y, b4.z, b4.w, c2.x, c2.y };
        float lo0, hi0, lo1, hi1;
        conv8(v,     lo0, hi0);
        conv8(v + 2, lo1, hi1);

        if (!LAST) *(float2*)(sout + j0) = make_float2(lo0, lo1);

        const int g0 = base + j0;
        if (j0 >= H) {                       // pair-uniform (H, j0 even)
            if ((unsigned)g0 < (unsigned)LEN) {
                dr[g0] = hi0;
                if (LAST) ar[g0] = lo0;
            }
            if ((unsigned)(g0 + 1) < (unsigned)LEN) {
                dr[g0 + 1] = hi1;
                if (LAST) ar[g0 + 1] = lo1;
            }
        }
    }
}

__global__ void __launch_bounds__(TPB)
dwt6_fused_kernel(const float* __restrict__ x, float* __restrict__ out) {
    __shared__ __align__(16) float s1[2240];  // S1=2234
    __shared__ __align__(16) float s2[1120];  // S2=1114
    __shared__ __align__(16) float s3[560];   // S3=554
    __shared__ __align__(16) float s4[288];   // S4=274
    __shared__ __align__(16) float s5[144];   // S5=134

    const int c   = blockIdx.x;
    const int r   = blockIdx.y;
    const int tid = threadIdx.x;
    const float* __restrict__ xr = x + (size_t)r * 262144;

    // ---- Level 1: gmem -> (s1, d1) ----
    {
        constexpr int LEN = 131075, H = 186, NP = 1117;  // S1 = 2234
        const int base = c * 2048 - H;                   // even
        float* __restrict__ dr = out + (size_t)8390848 + (size_t)r * LEN;

        for (int jp = tid; jp < NP; jp += TPB) {
            const int j0 = 2 * jp;
            const int g0 = base + j0;                    // even
            float lo0, hi0, lo1, hi1;
            // window x[2g0-6 .. 2g0+3]; fast path fully in-bounds
            if ((unsigned)(g0 - 3) <= 131067u) {         // g0 in [3, 131070]
                const float2 a2 = *(const float2*)(xr + 2 * g0 - 6);
                const float4 b4 = *(const float4*)(xr + 2 * g0 - 4);
                const float4 c4 = *(const float4*)(xr + 2 * g0);
                const float v[10] = { a2.x, a2.y, b4.x, b4.y, b4.z, b4.w,
                                      c4.x, c4.y, c4.z, c4.w };
                conv8(v,     lo0, hi0);
                conv8(v + 2, lo1, hi1);
            } else {
                float v[10];
                #pragma unroll
                for (int m = 0; m < 10; m++) {
                    const int idx = 2 * g0 - 6 + m;
                    v[m] = ((unsigned)idx < 262144u) ? __ldg(xr + idx) : 0.f;
                }
                conv8(v,     lo0, hi0);
                conv8(v + 2, lo1, hi1);
            }
            *(float2*)(s1 + j0) = make_float2(lo0, lo1);
            if (j0 >= H) {
                if ((unsigned)g0       < (unsigned)LEN) dr[g0]     = hi0;
                if ((unsigned)(g0 + 1) < (unsigned)LEN) dr[g0 + 1] = hi1;
            }
        }
    }
    __syncthreads();

    level_pair<16, 65541, 90, 4196224, false>(s1, s2, out, c, r, tid);  // d2
    __syncthreads();
    level_pair< 8, 32774, 42, 2098688, false>(s2, s3, out, c, r, tid);  // d3
    __syncthreads();
    level_pair< 4, 16390, 18, 1049728, false>(s3, s4, out, c, r, tid);  // d4
    __syncthreads();
    level_pair< 2,  8198,  6,  525056, false>(s4, s5, out, c, r, tid);  // d5
    __syncthreads();
    level_pair< 1,  4102,  0,  262528, true >(s5, (float*)0, out, c, r, tid);  // d6 + a
}

extern "C" void kernel_launch(void* const* d_in, const int* in_sizes, int n_in,
                              void* d_out, int out_size) {
    const float* x = (const float*)d_in[0];
    float* out = (float*)d_out;
    const int rows = in_sizes[0] / 262144;          // 64
    const int chunks = (4102 + TT - 1) / TT;        // 65
    dim3 grid(chunks, rows);
    dwt6_fused_kernel<<<grid, TPB>>>(x, out);
}